// round 17
// baseline (speedup 1.0000x reference)
#include <cuda_runtime.h>
#include <cuda_fp16.h>
#include <cstdint>

#define BB 64
#define TT 1024
#define EE 256
#define CIN 8
#define OUTD 63
#define NROW (BB*TT)          // 65536
#define ROWSTRIDE (BB*EE)     // 16384
#define LIF_WARM 160

#define LO_SCALE 4096.f
#define LO_INV   (1.f/4096.f)

// ---------------- scratch ----------------------------------------------------
__device__ float g_y[NROW * EE];                                // conv out [(t*B+b)][e]
__device__ __align__(16) __half g_spad[(TT + 2) * ROWSTRIDE];   // fp16 spikes, t-padded
__device__ __align__(16) __half g_wh[3 * 2 * 768 * 256];        // fp16 weights [layer][split][k][n]
__device__ float g_w0[3 * CIN * EE];
__device__ float g_psum[EE * 1024];                             // [e][row]; also lif partial counts
__device__ float g_psq[EE * 1024];
__device__ float g_sum[EE];
__device__ float g_sq[EE];

// ---------------- ptx helpers ------------------------------------------------
__device__ __forceinline__ uint32_t smem_u32(const void* p) {
    uint32_t a;
    asm("{ .reg .u64 t; cvta.to.shared.u64 t, %1; cvt.u32.u64 %0, t; }" : "=r"(a) : "l"(p));
    return a;
}
__device__ __forceinline__ void ldm4(uint32_t* r, uint32_t a) {
    asm volatile("ldmatrix.sync.aligned.m8n8.x4.shared.b16 {%0,%1,%2,%3}, [%4];"
                 : "=r"(r[0]), "=r"(r[1]), "=r"(r[2]), "=r"(r[3]) : "r"(a));
}
__device__ __forceinline__ void ldm4t(uint32_t* r, uint32_t a) {
    asm volatile("ldmatrix.sync.aligned.m8n8.x4.trans.shared.b16 {%0,%1,%2,%3}, [%4];"
                 : "=r"(r[0]), "=r"(r[1]), "=r"(r[2]), "=r"(r[3]) : "r"(a));
}
__device__ __forceinline__ void mma_h(float* d, const uint32_t* a, const uint32_t* b) {
    asm volatile("mma.sync.aligned.m16n8k16.row.col.f32.f16.f16.f32 "
                 "{%0,%1,%2,%3}, {%4,%5,%6,%7}, {%8,%9}, {%0,%1,%2,%3};"
                 : "+f"(d[0]), "+f"(d[1]), "+f"(d[2]), "+f"(d[3])
                 : "r"(a[0]), "r"(a[1]), "r"(a[2]), "r"(a[3]), "r"(b[0]), "r"(b[1]));
}
__device__ __forceinline__ void cpa16(uint32_t dst, const void* src) {
    asm volatile("cp.async.cg.shared.global [%0], [%1], 16;" :: "r"(dst), "l"(src));
}
#define CPA_COMMIT() asm volatile("cp.async.commit_group;" ::: "memory")
#define CPA_WAIT1()  asm volatile("cp.async.wait_group 1;" ::: "memory")

// ---------------- prep kernels -----------------------------------------------
__global__ void repack_wh_k(const float* __restrict__ w) {
    int idx = blockIdx.x * blockDim.x + threadIdx.x;     // 3*768*256
    if (idx >= 3 * 768 * 256) return;
    int n = idx & 255;
    int k = (idx >> 8) % 768;          // k = kpos*256 + c
    int i = idx / (768 * 256);
    int kpos = k >> 8;
    int c = k & 255;
    float wf = w[((i * 256 + n) * 256 + c) * 3 + kpos];
    __half h0 = __float2half_rn(wf);
    float lo = (wf - __half2float(h0)) * LO_SCALE;
    __half h1 = __float2half_rn(lo);
    g_wh[((size_t)(i * 2 + 0) * 768 + k) * 256 + n] = h0;
    g_wh[((size_t)(i * 2 + 1) * 768 + k) * 256 + n] = h1;
}

// merged: conv0 weight repack + spad time-pad zeroing
__global__ void prep_k(const float* __restrict__ w0) {
    int idx = blockIdx.x * blockDim.x + threadIdx.x;
    if (idx < ROWSTRIDE) g_spad[idx] = __float2half(0.f);
    else if (idx < 2 * ROWSTRIDE) g_spad[(TT + 1) * ROWSTRIDE + (idx - ROWSTRIDE)] = __float2half(0.f);
    if (idx < 3 * CIN * 256) {
        int o = idx & 255;
        int c = (idx >> 8) & 7;
        int k = idx >> 11;
        g_w0[idx] = w0[(o * CIN + c) * 3 + k];
    }
}

// ---------------- conv0: one CTA per t, weights in regs, fused stats -----------
__global__ void __launch_bounds__(256) conv0_k(const float* __restrict__ x,
                                               const float* __restrict__ bias) {
    __shared__ float xs[64][24];
    int t = blockIdx.x;
    int tid = threadIdx.x;
    float wr[24];
#pragma unroll
    for (int j = 0; j < 24; j++) wr[j] = g_w0[j * 256 + tid];
    for (int q = tid; q < 64 * 24; q += 256) {
        int bl = q / 24, rem = q % 24;
        int k = rem >> 3, c = rem & 7;
        int ttm = t - 1 + k;
        float v = 0.f;
        if (ttm >= 0 && ttm < TT) v = x[((bl) * TT + ttm) * CIN + c];
        xs[bl][rem] = v;
    }
    __syncthreads();
    float bo = bias[tid];
    float s = 0.f, qq = 0.f;
#pragma unroll 2
    for (int r = 0; r < 64; r++) {
        float acc = bo;
#pragma unroll
        for (int j = 0; j < 24; j++) acc += wr[j] * xs[r][j];
        g_y[(size_t)(t * BB + r) * EE + tid] = acc;
        s += acc;
        qq += acc * acc;
    }
    g_psum[(size_t)tid * 1024 + t] = s;
    g_psq[(size_t)tid * 1024 + t] = qq;
}

// ---------------- fp16 scaled-2-split MMA conv GEMM ------------------------------
// CTA tile 128m x 64n, 256 thr (8 warps, 32x32 each), K-chunk 32, 3-stage, 2 CTA/SM.
#define APITCH 40                       // 32 data halves + 8 pad
#define BPITCH 72                       // 64 data halves + 8 pad
#define A_H 5120                        // halves: A tile per stage (128*40)
#define B_SP 2304                       // halves: one split B tile (32*72)
#define ST_H (A_H + 2 * B_SP)           // 9728 halves per stage
#define NSTAGE 3
#define SMEM_HALVES (NSTAGE * ST_H)     // 29184
#define SMEM_BYTES (SMEM_HALVES * 2)    // 58368

__global__ void __launch_bounds__(256, 2) conv_mma_k(int layer, const float* __restrict__ bias) {
    extern __shared__ __half sm[];
    const int tid = threadIdx.x;
    const int lane = tid & 31;
    const int wid = tid >> 5;
    const int wm = wid & 3;          // warp M group (32 rows)
    const int wn = wid >> 2;         // warp N group (0..1, 32 cols)
    const int mt = blockIdx.y;       // 512 M tiles
    const int nb = blockIdx.x;       // 4 N tiles of 64

    const uint4* __restrict__ wsrc = (const uint4*)(g_wh + (size_t)layer * 2 * 768 * 256);

    float acch[2][4][4], accl[2][4][4];
#pragma unroll
    for (int mi = 0; mi < 2; mi++)
#pragma unroll
        for (int u = 0; u < 4; u++)
#pragma unroll
            for (int q = 0; q < 4; q++) { acch[mi][u][q] = 0.f; accl[mi][u][q] = 0.f; }

    const uint32_t smb = smem_u32(sm);

    // one 32-wide K chunk into stage st; ck in 0..23
    auto issue = [&](int ck, int st) {
        int kpos = ck >> 3, c0 = (ck & 7) << 5;
        uint32_t base = smb + (uint32_t)(st * ST_H) * 2;
        // A: 512 x 16B (128 rows x 4 granules), 2 per thread
#pragma unroll
        for (int it = 0; it < 2; it++) {
            int u = tid + it * 256;
            int row = u >> 2, jg = u & 3;
            cpa16(base + (row * APITCH + jg * 8) * 2,
                  g_spad + (size_t)(2 * mt + (row >> 6) + kpos) * ROWSTRIDE
                         + (row & 63) * 256 + c0 + jg * 8);
        }
        // B: 512 x 16B (2 splits x 32 k x 8 granules of 64 cols), 2 per thread
#pragma unroll
        for (int it = 0; it < 2; it++) {
            int u = tid + it * 256;
            int s = u >> 8, rest = u & 255;
            int kk = rest >> 3, g = rest & 7;
            cpa16(base + (A_H + s * B_SP + kk * BPITCH + g * 8) * 2,
                  wsrc + (size_t)(s * 768 + kpos * 256 + c0 + kk) * 32 + nb * 8 + g);
        }
    };

#pragma unroll
    for (int p = 0; p < 2; p++) { issue(p, p); CPA_COMMIT(); }

    int st = 0;
    for (int ck = 0; ck < 24; ck++) {
        CPA_WAIT1();
        __syncthreads();
        if (ck + 2 < 24) {
            int st2 = st + 2; if (st2 >= 3) st2 -= 3;
            issue(ck + 2, st2);
        }
        CPA_COMMIT();

        const __half* Asm = sm + st * ST_H;
        const __half* Bsm = Asm + A_H;
#pragma unroll
        for (int kh = 0; kh < 2; kh++) {
            uint32_t afr[2][4];
#pragma unroll
            for (int mi = 0; mi < 2; mi++) {
                uint32_t ad = smem_u32(Asm + (wm * 32 + mi * 16 + (lane & 15)) * APITCH
                                       + kh * 16 + (lane >> 4) * 8);
                ldm4(afr[mi], ad);
            }
#pragma unroll
            for (int s = 0; s < 2; s++) {
                uint32_t bfr[2][4];
#pragma unroll
                for (int q = 0; q < 2; q++) {
                    uint32_t bd = smem_u32(Bsm + s * B_SP + (kh * 16 + (lane & 15)) * BPITCH
                                           + wn * 32 + q * 16 + (lane >> 4) * 8);
                    ldm4t(bfr[q], bd);
                }
                if (s == 0) {
#pragma unroll
                    for (int mi = 0; mi < 2; mi++)
#pragma unroll
                        for (int q = 0; q < 2; q++)
#pragma unroll
                            for (int h = 0; h < 2; h++)
                                mma_h(acch[mi][q * 2 + h], afr[mi], &bfr[q][h * 2]);
                } else {
#pragma unroll
                    for (int mi = 0; mi < 2; mi++)
#pragma unroll
                        for (int q = 0; q < 2; q++)
#pragma unroll
                            for (int h = 0; h < 2; h++)
                                mma_h(accl[mi][q * 2 + h], afr[mi], &bfr[q][h * 2]);
                }
            }
        }
        if (++st >= 3) st -= 3;
    }

    // epilogue: combine splits, write y, fused column stats
    __syncthreads();
    float* red = (float*)sm;      // [wm][64] sums @0, sq @256

    const int m0 = mt * 128 + wm * 32 + (lane >> 2);
    float csum[8], csq[8];
#pragma unroll
    for (int j = 0; j < 8; j++) { csum[j] = 0.f; csq[j] = 0.f; }

#pragma unroll
    for (int u = 0; u < 4; u++) {
        int n = nb * 64 + wn * 32 + (u >> 1) * 16 + (u & 1) * 8 + (lane & 3) * 2;
        float2 bv = *(const float2*)(bias + n);
#pragma unroll
        for (int mi = 0; mi < 2; mi++) {
            int r0 = m0 + mi * 16;
            float v00 = fmaf(accl[mi][u][0], LO_INV, acch[mi][u][0]) + bv.x;
            float v01 = fmaf(accl[mi][u][1], LO_INV, acch[mi][u][1]) + bv.y;
            float v10 = fmaf(accl[mi][u][2], LO_INV, acch[mi][u][2]) + bv.x;
            float v11 = fmaf(accl[mi][u][3], LO_INV, acch[mi][u][3]) + bv.y;
            float2 w0, w1;
            w0.x = v00; w0.y = v01;
            w1.x = v10; w1.y = v11;
            *(float2*)(g_y + (size_t)r0 * 256 + n) = w0;
            *(float2*)(g_y + (size_t)(r0 + 8) * 256 + n) = w1;
            csum[u * 2 + 0] += v00 + v10;
            csum[u * 2 + 1] += v01 + v11;
            csq[u * 2 + 0] += v00 * v00 + v10 * v10;
            csq[u * 2 + 1] += v01 * v01 + v11 * v11;
        }
    }
#pragma unroll
    for (int off = 4; off < 32; off <<= 1)
#pragma unroll
        for (int j = 0; j < 8; j++) {
            csum[j] += __shfl_xor_sync(0xffffffffu, csum[j], off);
            csq[j]  += __shfl_xor_sync(0xffffffffu, csq[j],  off);
        }
    if (lane < 4) {
#pragma unroll
        for (int j = 0; j < 8; j++) {
            int u = j >> 1;
            int cl = wn * 32 + (u >> 1) * 16 + (u & 1) * 8 + lane * 2 + (j & 1);  // 0..63
            red[wm * 64 + cl] = csum[j];
            red[256 + wm * 64 + cl] = csq[j];
        }
    }
    __syncthreads();
    if (tid < 64) {
        float s = red[tid] + red[64 + tid] + red[128 + tid] + red[192 + tid];
        float q = red[256 + tid] + red[320 + tid] + red[384 + tid] + red[448 + tid];
        g_psum[(size_t)(nb * 64 + tid) * 1024 + mt] = s;
        g_psq[(size_t)(nb * 64 + tid) * 1024 + mt] = q;
    }
}

// ---------------- BN stats finalize: 1 block per channel ------------------------
__global__ void __launch_bounds__(128) stats2_k(int nrows) {
    __shared__ float ss[128], qq[128];
    int e = blockIdx.x;
    int t = threadIdx.x;
    const float* ps = g_psum + (size_t)e * 1024;
    const float* pq = g_psq + (size_t)e * 1024;
    float s = 0.f, q = 0.f;
    for (int r = t; r < nrows; r += 128) { s += ps[r]; q += pq[r]; }
    ss[t] = s; qq[t] = q;
    __syncthreads();
#pragma unroll
    for (int off = 64; off > 0; off >>= 1) {
        if (t < off) { ss[t] += ss[t + off]; qq[t] += qq[t + off]; }
        __syncthreads();
    }
    if (t == 0) { g_sum[e] = ss[0]; g_sq[e] = qq[0]; }
}

// ---------------- BN apply + LIF, time-chunked, 2 channels per thread -----------
// grid = 4 chunks x 64 b x 2 e-halves = 512 blocks x 64 threads; float2 loads.
__global__ void __launch_bounds__(64) lif_k(const float* __restrict__ gamma,
                                            const float* __restrict__ beta,
                                            int write_rate) {
    int blk = blockIdx.x;
    int chunk = blk >> 7;                      // 0..3
    int r = blk & 127;
    int b = r >> 1;
    int e = ((r & 1) << 7) + threadIdx.x * 2;  // even channel index
    float2 gm = *(const float2*)(gamma + e);
    float2 bt = *(const float2*)(beta + e);
    float2 su = *(const float2*)(g_sum + e);
    float2 sq = *(const float2*)(g_sq + e);
    float mu0 = su.x * (1.f / NROW), mu1 = su.y * (1.f / NROW);
    float var0 = sq.x * (1.f / NROW) - mu0 * mu0;
    float var1 = sq.y * (1.f / NROW) - mu1 * mu1;
    float sc0 = gm.x / sqrtf(var0 + 1e-5f);
    float sc1 = gm.y / sqrtf(var1 + 1e-5f);
    float sh0 = fmaf(-mu0, sc0, bt.x);
    float sh1 = fmaf(-mu1, sc1, bt.y);

    const int t0 = chunk << 8;
    const int tw = (chunk == 0) ? 0 : (t0 - LIF_WARM);
    const int tend = t0 + 256;
    const float2* yp = (const float2*)(g_y + (size_t)b * 256 + e);   // stride 8192 float2
    __half* sp = g_spad + (size_t)ROWSTRIDE + b * 256 + e;

    float2 buf[16];
#pragma unroll
    for (int i = 0; i < 16; i++) buf[i] = yp[(size_t)(tw + i) * 8192];
    float v0 = 0.f, v1 = 0.f, c0 = 0.f, c1 = 0.f;

#pragma unroll 16
    for (int t = tw; t < t0; t++) {
        float2 xv = buf[t & 15];
        buf[t & 15] = yp[(size_t)(t + 16) * 8192];
        v0 = 0.5f * (v0 + fmaf(xv.x, sc0, sh0));
        v1 = 0.5f * (v1 + fmaf(xv.y, sc1, sh1));
        v0 = (v0 >= 1.f) ? 0.f : v0;
        v1 = (v1 >= 1.f) ? 0.f : v1;
    }
    if (write_rate) {
#pragma unroll 16
        for (int t = t0; t < tend; t++) {
            float2 xv = buf[t & 15];
            if (t + 16 < tend) buf[t & 15] = yp[(size_t)(t + 16) * 8192];
            v0 = 0.5f * (v0 + fmaf(xv.x, sc0, sh0));
            v1 = 0.5f * (v1 + fmaf(xv.y, sc1, sh1));
            float s0 = (v0 >= 1.f) ? 1.f : 0.f;
            float s1 = (v1 >= 1.f) ? 1.f : 0.f;
            c0 += s0; c1 += s1;
            v0 = (v0 >= 1.f) ? 0.f : v0;
            v1 = (v1 >= 1.f) ? 0.f : v1;
        }
        float2 cw; cw.x = c0; cw.y = c1;
        *(float2*)(g_psum + chunk * 16384 + b * 256 + e) = cw;   // partial counts
    } else {
#pragma unroll 16
        for (int t = t0; t < tend; t++) {
            float2 xv = buf[t & 15];
            if (t + 16 < tend) buf[t & 15] = yp[(size_t)(t + 16) * 8192];
            v0 = 0.5f * (v0 + fmaf(xv.x, sc0, sh0));
            v1 = 0.5f * (v1 + fmaf(xv.y, sc1, sh1));
            float s0 = (v0 >= 1.f) ? 1.f : 0.f;
            float s1 = (v1 >= 1.f) ? 1.f : 0.f;
            __half2 hs = __floats2half2_rn(s0, s1);
            *(__half2*)(sp + (size_t)t * ROWSTRIDE) = hs;
            v0 = (v0 >= 1.f) ? 0.f : v0;
            v1 = (v1 >= 1.f) ? 0.f : v1;
        }
    }
}

// ---------------- head: combine chunk partial counts + linear --------------------
__global__ void head_k(const float* __restrict__ hw, const float* __restrict__ hb,
                       float* __restrict__ out) {
    __shared__ float rs[EE];
    int b = blockIdx.x, tid = threadIdx.x;   // 64 threads
    for (int j = tid; j < EE; j += 64) {
        float c = g_psum[0 * 16384 + b * 256 + j] + g_psum[1 * 16384 + b * 256 + j]
                + g_psum[2 * 16384 + b * 256 + j] + g_psum[3 * 16384 + b * 256 + j];
        rs[j] = c * (1.f / TT);
    }
    __syncthreads();
    if (tid < OUTD) {
        float acc = hb[tid];
#pragma unroll 8
        for (int e2 = 0; e2 < EE; e2++) acc += rs[e2] * hw[tid * EE + e2];
        out[b * OUTD + tid] = acc;
    }
}

// ---------------- launch ---------------------------------------------------------
extern "C" void kernel_launch(void* const* d_in, const int* in_sizes, int n_in,
                              void* d_out, int out_size) {
    const float *x = 0, *conv0_w = 0, *conv0_b = 0, *convs_w = 0, *convs_b = 0;
    const float *gamma = 0, *beta = 0, *head_w = 0, *head_b = 0;
    int n1024_seen = 0;
    int alphabetical = (n_in > 0 && in_sizes[0] == 1024);
    for (int i = 0; i < n_in; i++) {
        const float* p = (const float*)d_in[i];
        switch (in_sizes[i]) {
            case 524288: x = p; break;
            case 6144:   conv0_w = p; break;
            case 256:    conv0_b = p; break;
            case 589824: convs_w = p; break;
            case 768:    convs_b = p; break;
            case 16128:  head_w = p; break;
            case 63:     head_b = p; break;
            case 1024:
                if (n1024_seen == 0) { if (alphabetical) beta = p; else gamma = p; }
                else                 { if (alphabetical) gamma = p; else beta = p; }
                n1024_seen++;
                break;
            default: break;
        }
    }
    float* out = (float*)d_out;

    cudaFuncSetAttribute(conv_mma_k, cudaFuncAttributeMaxDynamicSharedMemorySize, SMEM_BYTES);

    prep_k<<<(2 * ROWSTRIDE + 255) / 256, 256>>>(conv0_w);
    conv0_k<<<TT, 256>>>(x, conv0_b);
    stats2_k<<<256, 128>>>(1024);
    lif_k<<<512, 64>>>(gamma + 0 * EE, beta + 0 * EE, 0);

    repack_wh_k<<<(3 * 768 * 256 + 255) / 256, 256>>>(convs_w);

    for (int i = 0; i < 3; i++) {
        conv_mma_k<<<dim3(4, 512), 256, SMEM_BYTES>>>(i, convs_b + i * EE);
        stats2_k<<<256, 128>>>(512);
        lif_k<<<512, 64>>>(gamma + (i + 1) * EE, beta + (i + 1) * EE, (i == 2) ? 1 : 0);
    }

    head_k<<<BB, 64>>>(head_w, head_b, out);
}